// round 3
// baseline (speedup 1.0000x reference)
#include <cuda_runtime.h>
#include <cstdint>

// Scratch in __device__ globals (no allocation allowed).
__device__ double g_psum;
__device__ double g_gsum;
__device__ double g_inter;
__device__ float  g_iou_sum;

__global__ void init_kernel() {
    g_psum = 0.0;
    g_gsum = 0.0;
    g_inter = 0.0;
    g_iou_sum = 0.0f;
}

// ---------------------------------------------------------------------------
// Kernel 1: global sums over P, G, P*G. float4 grid-stride, warp-shuffle
// block reduce, per-block double atomics.
// ---------------------------------------------------------------------------
__global__ __launch_bounds__(256) void global_reduce_kernel(
    const float4* __restrict__ P, const float4* __restrict__ G, long n4)
{
    float ps = 0.f, gs = 0.f, is = 0.f;
    long idx    = (long)blockIdx.x * blockDim.x + threadIdx.x;
    long stride = (long)gridDim.x * blockDim.x;
    for (long i = idx; i < n4; i += stride) {
        float4 p = P[i];
        float4 g = G[i];
        ps += (p.x + p.y) + (p.z + p.w);
        gs += (g.x + g.y) + (g.z + g.w);
        is += p.x * g.x + p.y * g.y + p.z * g.z + p.w * g.w;
    }

    // warp reduce
    #pragma unroll
    for (int o = 16; o > 0; o >>= 1) {
        ps += __shfl_down_sync(0xffffffffu, ps, o);
        gs += __shfl_down_sync(0xffffffffu, gs, o);
        is += __shfl_down_sync(0xffffffffu, is, o);
    }

    __shared__ float sp[8], sg[8], si[8];
    int wid = threadIdx.x >> 5;
    int lid = threadIdx.x & 31;
    if (lid == 0) { sp[wid] = ps; sg[wid] = gs; si[wid] = is; }
    __syncthreads();
    if (wid == 0) {
        int nw = blockDim.x >> 5;
        ps = (lid < nw) ? sp[lid] : 0.f;
        gs = (lid < nw) ? sg[lid] : 0.f;
        is = (lid < nw) ? si[lid] : 0.f;
        #pragma unroll
        for (int o = 4; o > 0; o >>= 1) {
            ps += __shfl_down_sync(0xffffffffu, ps, o);
            gs += __shfl_down_sync(0xffffffffu, gs, o);
            is += __shfl_down_sync(0xffffffffu, is, o);
        }
        if (lid == 0) {
            atomicAdd(&g_psum,  (double)ps);
            atomicAdd(&g_gsum,  (double)gs);
            atomicAdd(&g_inter, (double)is);
        }
    }
}

// ---------------------------------------------------------------------------
// Kernel 2: region IoU. One block per (b, k). Replicates _bounds exactly:
//   start = max(c-20, 0); end = min(c+20, dim); new = end-start
//   odd_small = (new odd) && (new < 40)
//   if (odd_small && start==0) end -= 1;
//   if (odd_small && end==dim) start += 1;   // uses UPDATED end, per reference
// ---------------------------------------------------------------------------
__global__ __launch_bounds__(256) void region_kernel(
    const float* __restrict__ P, const float* __restrict__ G,
    const int* __restrict__ cents, int K, int H, int W)
{
    int b = blockIdx.x / K;
    int k = blockIdx.x % K;
    int cy = cents[(b * K + k) * 2 + 0];
    int cx = cents[(b * K + k) * 2 + 1];

    int sy = max(cy - 20, 0);
    int ey = min(cy + 20, H);
    {
        int ny = ey - sy;
        bool odd = ((ny & 1) != 0) && (ny < 40);
        if (odd && sy == 0) ey -= 1;
        if (odd && ey == H) sy += 1;
    }
    int sx = max(cx - 20, 0);
    int ex = min(cx + 20, W);
    {
        int nx = ex - sx;
        bool odd = ((nx & 1) != 0) && (nx < 40);
        if (odd && sx == 0) ex -= 1;
        if (odd && ex == W) sx += 1;
    }

    int wy = ey - sy;
    int wx = ex - sx;
    int cnt = wy * wx;

    const float* Pb = P + (size_t)b * H * W;
    const float* Gb = G + (size_t)b * H * W;

    float ps = 0.f, gs = 0.f, is = 0.f;
    for (int i = threadIdx.x; i < cnt; i += blockDim.x) {
        int yy = sy + i / wx;
        int xx = sx + i % wx;
        size_t off = (size_t)yy * W + xx;
        float p = Pb[off];
        float g = Gb[off];
        ps += p; gs += g; is += p * g;
    }

    #pragma unroll
    for (int o = 16; o > 0; o >>= 1) {
        ps += __shfl_down_sync(0xffffffffu, ps, o);
        gs += __shfl_down_sync(0xffffffffu, gs, o);
        is += __shfl_down_sync(0xffffffffu, is, o);
    }
    __shared__ float sp[8], sg[8], si[8];
    int wid = threadIdx.x >> 5;
    int lid = threadIdx.x & 31;
    if (lid == 0) { sp[wid] = ps; sg[wid] = gs; si[wid] = is; }
    __syncthreads();
    if (threadIdx.x == 0) {
        int nw = blockDim.x >> 5;
        float tp = 0.f, tg = 0.f, ti = 0.f;
        for (int w = 0; w < nw; w++) { tp += sp[w]; tg += sg[w]; ti += si[w]; }
        float iou = (ti + 1.0f) / (tp + tg - ti + 1.0f);
        atomicAdd(&g_iou_sum, iou);
    }
}

// ---------------------------------------------------------------------------
// Kernel 3: combine into the scalar output.
// ---------------------------------------------------------------------------
__global__ void finalize_kernel(float* out, int BK) {
    double inter = g_inter;
    double psum  = g_psum;
    double gsum  = g_gsum;
    double loss_global = 1.0 - (inter + 1.0) / (psum + gsum - inter + 1.0);
    double loss_region = 1.0 - (double)g_iou_sum / (double)BK;
    out[0] = (float)(loss_global + loss_region);
}

extern "C" void kernel_launch(void* const* d_in, const int* in_sizes, int n_in,
                              void* d_out, int out_size)
{
    const float* preds = (const float*)d_in[0];
    const float* gt    = (const float*)d_in[1];
    const int*   cents = (const int*)d_in[2];
    float* out = (float*)d_out;

    const int H = 1024, W = 1024;
    long n = (long)in_sizes[0];
    int B = (int)(n / ((long)H * W));
    int K = in_sizes[2] / (2 * B);
    long n4 = n / 4;

    init_kernel<<<1, 1>>>();

    int threads = 256;
    int blocks = 2048;   // ~14 float4 per thread, good MLP
    global_reduce_kernel<<<blocks, threads>>>(
        (const float4*)preds, (const float4*)gt, n4);

    region_kernel<<<B * K, 256>>>(preds, gt, cents, K, H, W);

    finalize_kernel<<<1, 1>>>(out, B * K);
}

// round 5
// speedup vs baseline: 1.2628x; 1.2628x over previous
#include <cuda_runtime.h>
#include <cstdint>

// Accumulators in __device__ globals (no allocation allowed). Zero-initialized
// at module load; the "last block" resets them after finalizing so every
// graph replay starts from a clean state.
__device__ double       g_psum  = 0.0;
__device__ double       g_gsum  = 0.0;
__device__ double       g_inter = 0.0;
__device__ float        g_iou_sum = 0.0f;
__device__ unsigned int g_done = 0u;

// ---------------------------------------------------------------------------
// Single fused kernel.
//   blocks [0, NB)        : global sums of P, G, P*G (float4 streaming loads)
//   blocks [NB, NB+B*K)   : per-(b,k) region soft-IoU
//   last block to finish  : finalize scalar, write out[0], reset globals
// ---------------------------------------------------------------------------
__global__ __launch_bounds__(256) void fused_iou_kernel(
    const float* __restrict__ Pf, const float* __restrict__ Gf,
    const int* __restrict__ cents,
    long n4, int NB, int K, int H, int W, int BK,
    float* __restrict__ out)
{
    const int tid = threadIdx.x;
    const int wid = tid >> 5;
    const int lid = tid & 31;
    __shared__ float sp[8], sg[8], si[8];

    if (blockIdx.x < (unsigned)NB) {
        // ---------------- global reduction ----------------
        const float4* __restrict__ P = (const float4*)Pf;
        const float4* __restrict__ G = (const float4*)Gf;
        float ps = 0.f, gs = 0.f, is = 0.f;
        long idx    = (long)blockIdx.x * blockDim.x + tid;
        long stride = (long)NB * blockDim.x;
        for (long i = idx; i < n4; i += stride) {
            float4 p = __ldcs(&P[i]);   // streaming: no L2 retention benefit
            float4 g = __ldcs(&G[i]);
            ps += (p.x + p.y) + (p.z + p.w);
            gs += (g.x + g.y) + (g.z + g.w);
            is += p.x * g.x + p.y * g.y + p.z * g.z + p.w * g.w;
        }
        #pragma unroll
        for (int o = 16; o > 0; o >>= 1) {
            ps += __shfl_down_sync(0xffffffffu, ps, o);
            gs += __shfl_down_sync(0xffffffffu, gs, o);
            is += __shfl_down_sync(0xffffffffu, is, o);
        }
        if (lid == 0) { sp[wid] = ps; sg[wid] = gs; si[wid] = is; }
        __syncthreads();
        if (wid == 0) {
            int nw = blockDim.x >> 5;
            ps = (lid < nw) ? sp[lid] : 0.f;
            gs = (lid < nw) ? sg[lid] : 0.f;
            is = (lid < nw) ? si[lid] : 0.f;
            #pragma unroll
            for (int o = 4; o > 0; o >>= 1) {
                ps += __shfl_down_sync(0xffffffffu, ps, o);
                gs += __shfl_down_sync(0xffffffffu, gs, o);
                is += __shfl_down_sync(0xffffffffu, is, o);
            }
            if (lid == 0) {
                atomicAdd(&g_psum,  (double)ps);
                atomicAdd(&g_gsum,  (double)gs);
                atomicAdd(&g_inter, (double)is);
            }
        }
    } else {
        // ---------------- region IoU for one (b, k) ----------------
        int r = blockIdx.x - NB;
        int b = r / K;
        int k = r % K;
        int cy = cents[(b * K + k) * 2 + 0];
        int cx = cents[(b * K + k) * 2 + 1];

        // Replicates _bounds exactly (parity fix uses the UPDATED end).
        int sy = max(cy - 20, 0), ey = min(cy + 20, H);
        {
            int ny = ey - sy;
            bool odd = ((ny & 1) != 0) && (ny < 40);
            if (odd && sy == 0) ey -= 1;
            if (odd && ey == H) sy += 1;
        }
        int sx = max(cx - 20, 0), ex = min(cx + 20, W);
        {
            int nx = ex - sx;
            bool odd = ((nx & 1) != 0) && (nx < 40);
            if (odd && sx == 0) ex -= 1;
            if (odd && ex == W) sx += 1;
        }

        int wy = ey - sy, wx = ex - sx;
        int cnt = wy * wx;
        const float* Pb = Pf + (size_t)b * H * W;
        const float* Gb = Gf + (size_t)b * H * W;

        float ps = 0.f, gs = 0.f, is = 0.f;
        for (int i = tid; i < cnt; i += blockDim.x) {
            int yy = sy + i / wx;
            int xx = sx + i % wx;
            size_t off = (size_t)yy * W + xx;
            float p = Pb[off];
            float g = Gb[off];
            ps += p; gs += g; is += p * g;
        }
        #pragma unroll
        for (int o = 16; o > 0; o >>= 1) {
            ps += __shfl_down_sync(0xffffffffu, ps, o);
            gs += __shfl_down_sync(0xffffffffu, gs, o);
            is += __shfl_down_sync(0xffffffffu, is, o);
        }
        if (lid == 0) { sp[wid] = ps; sg[wid] = gs; si[wid] = is; }
        __syncthreads();
        if (tid == 0) {
            int nw = blockDim.x >> 5;
            float tp = 0.f, tg = 0.f, ti = 0.f;
            for (int w = 0; w < nw; w++) { tp += sp[w]; tg += sg[w]; ti += si[w]; }
            float iou = (ti + 1.0f) / (tp + tg - ti + 1.0f);
            atomicAdd(&g_iou_sum, iou);
        }
    }

    // ---------------- last-block finalize + reset ----------------
    __syncthreads();
    if (tid == 0) {
        __threadfence();
        unsigned int total = (unsigned)NB + (unsigned)BK;
        unsigned int prev = atomicAdd(&g_done, 1u);
        if (prev == total - 1u) {
            // All other blocks' atomics are visible (fence-before-increment,
            // and we observed every increment).
            double inter = atomicAdd(&g_inter, 0.0);
            double psum  = atomicAdd(&g_psum, 0.0);
            double gsum  = atomicAdd(&g_gsum, 0.0);
            float  iou   = atomicAdd(&g_iou_sum, 0.0f);
            double loss_global = 1.0 - (inter + 1.0) / (psum + gsum - inter + 1.0);
            double loss_region = 1.0 - (double)iou / (double)BK;
            out[0] = (float)(loss_global + loss_region);
            // Reset for next graph replay (we are the only block still writing).
            g_psum = 0.0; g_gsum = 0.0; g_inter = 0.0;
            g_iou_sum = 0.0f;
            __threadfence();
            g_done = 0u;
        }
    }
}

extern "C" void kernel_launch(void* const* d_in, const int* in_sizes, int n_in,
                              void* d_out, int out_size)
{
    const float* preds = (const float*)d_in[0];
    const float* gt    = (const float*)d_in[1];
    const int*   cents = (const int*)d_in[2];
    float* out = (float*)d_out;

    const int H = 1024, W = 1024;
    long n  = (long)in_sizes[0];
    int  B  = (int)(n / ((long)H * W));
    int  K  = in_sizes[2] / (2 * B);
    int  BK = B * K;
    long n4 = n / 4;

    const int NB = 2048;   // reduce blocks; + BK region blocks
    fused_iou_kernel<<<NB + BK, 256>>>(preds, gt, cents, n4, NB, K, H, W, BK, out);
}